// round 8
// baseline (speedup 1.0000x reference)
#include <cuda_runtime.h>
#include <cuda_fp16.h>
#include <math.h>
#include <stdint.h>

#define N_NODES 50000
#define IN_CH   128
#define HID     256
#define QK_N    512
#define E_MAX   1600000

// ------------------------- scratch (device globals) -------------------------
__device__ __half g_x16[N_NODES * IN_CH];        // x, fp16
__device__ __half g_xa [N_NODES * IN_CH];        // P.x, fp16
__device__ __half g_h16[N_NODES * HID];          // h = relu((Px)W1 + c b1), fp16
__device__ __half g_ha [N_NODES * HID];          // P.h, fp16
__device__ __half g_z16[N_NODES * HID];          // z, fp16
__device__ __half g_qkvh[N_NODES * QK_N];        // Q(256) K(256) per node, fp16
__device__ float g_qkself[N_NODES * 4];
__device__ float g_vw[N_NODES * 4];
__device__ float g_dinv[N_NODES];
__device__ float g_c[N_NODES];                   // bias aggregation coefficient
__device__ int   g_deg [N_NODES];
__device__ int   g_rowptr[N_NODES + 1];
__device__ int   g_cursor[N_NODES];
__device__ int   g_colsrc[E_MAX];
__device__ int   g_bsums[64];
__device__ int   g_boff[64];

__device__ __half g_w1[HID * IN_CH];             // [N=256][K=128] fp16
__device__ __half g_w2[HID * HID];               // [N=256][K=256] fp16
__device__ __half g_wqk[QK_N * HID];             // [N=512][K=256] fp16
__device__ float g_biasqk[QK_N];
__device__ float g_wv[HID * 4];                  // folded V weights [k][h]
__device__ float g_bvw[4];
__device__ float g_bsum;

// ------------------------- helpers -------------------------
__device__ __forceinline__ uint32_t smem_u32(const void* p) {
    uint32_t a;
    asm("{ .reg .u64 t; cvta.to.shared.u64 t, %1; cvt.u32.u64 %0, t; }" : "=r"(a) : "l"(p));
    return a;
}
__device__ __forceinline__ void ldsm_x4(uint32_t* r, uint32_t addr) {
    asm volatile("ldmatrix.sync.aligned.m8n8.x4.shared.b16 {%0,%1,%2,%3}, [%4];"
        : "=r"(r[0]), "=r"(r[1]), "=r"(r[2]), "=r"(r[3]) : "r"(addr));
}
__device__ __forceinline__ void ldsm_x2(uint32_t* r, uint32_t addr) {
    asm volatile("ldmatrix.sync.aligned.m8n8.x2.shared.b16 {%0,%1}, [%2];"
        : "=r"(r[0]), "=r"(r[1]) : "r"(addr));
}
__device__ __forceinline__ void mma_f16(float* d, const uint32_t* a, const uint32_t* b) {
    asm volatile("mma.sync.aligned.m16n8k16.row.col.f32.f16.f16.f32 "
        "{%0,%1,%2,%3}, {%4,%5,%6,%7}, {%8,%9}, {%0,%1,%2,%3};"
        : "+f"(d[0]), "+f"(d[1]), "+f"(d[2]), "+f"(d[3])
        : "r"(a[0]), "r"(a[1]), "r"(a[2]), "r"(a[3]), "r"(b[0]), "r"(b[1]));
}
__device__ __forceinline__ void cp16(uint32_t dst, const void* src) {
    asm volatile("cp.async.cg.shared.global [%0], [%1], 16;" :: "r"(dst), "l"(src));
}
__device__ __forceinline__ void cp16p(uint32_t dst, const void* src, bool pred) {
    int sz = pred ? 16 : 0;
    asm volatile("cp.async.cg.shared.global [%0], [%1], 16, %2;" :: "r"(dst), "l"(src), "r"(sz));
}

// ------------------------- weight prep -------------------------
// wsum + bsum + folded V weights, single block of 256 threads
__global__ void k_wsum_vw(const float* __restrict__ opw, const float* __restrict__ opb,
                          const float* __restrict__ ipw, const float* __restrict__ ipb) {
    __shared__ float ws[256];
    __shared__ float red[256];
    int i = threadIdx.x;
    float s = 0.f;
    #pragma unroll 4
    for (int j = 0; j < HID; j++) s += opw[j * HID + i];
    ws[i] = s;
    red[i] = opb[i];
    __syncthreads();
    for (int off = 128; off > 0; off >>= 1) {
        if (i < off) red[i] += red[i + off];
        __syncthreads();
    }
    if (i == 0) g_bsum = red[0];
    // folded V: g_wv[k][h] = sum_d ws[h*64+d] * ipw[(512+h*64+d)*256 + k]
    int k = i;
    #pragma unroll
    for (int h = 0; h < 4; h++) {
        float acc = 0.f;
        #pragma unroll 8
        for (int d = 0; d < 64; d++)
            acc += ws[h * 64 + d] * ipw[(size_t)(512 + h * 64 + d) * HID + k];
        g_wv[k * 4 + h] = acc;
    }
    if (i < 4) {
        float b = 0.f;
        for (int d = 0; d < 64; d++)
            b += ws[i * 64 + d] * ipb[512 + i * 64 + d];
        g_bvw[i] = b;
    }
}

// merged: W1^T (blocks 0..31), W2^T (blocks 32..95), Wqk copy (blocks 96..223)
__global__ void k_prep_w(const float* __restrict__ W1, const float* __restrict__ W2,
                         const float* __restrict__ ipw, const float* __restrict__ ipb) {
    int b = blockIdx.x;
    int tid = threadIdx.x;
    if (b < 96) {
        __shared__ float tile[32][33];
        const float* src;
        __half* dst;
        int n0, k0, Kd;
        if (b < 32) { src = W1; dst = g_w1; Kd = IN_CH; n0 = (b & 7) * 32; k0 = (b >> 3) * 32; }
        else { int bb = b - 32; src = W2; dst = g_w2; Kd = HID; n0 = (bb & 7) * 32; k0 = (bb >> 3) * 32; }
        int tx = tid & 31, ty = tid >> 5;
        #pragma unroll
        for (int i = 0; i < 4; i++) {
            int k = k0 + ty + i * 8;
            tile[ty + i * 8][tx] = src[(size_t)k * HID + n0 + tx];
        }
        __syncthreads();
        #pragma unroll
        for (int i = 0; i < 4; i++) {
            int n = n0 + ty + i * 8;
            dst[(size_t)n * Kd + k0 + tx] = __float2half(tile[tx][ty + i * 8]);
        }
    } else {
        int j = (b - 96) * 1024 + tid * 4;
        float4 v = *(const float4*)(ipw + j);
        __half2 lo = __floats2half2_rn(v.x, v.y);
        __half2 hi = __floats2half2_rn(v.z, v.w);
        uint2 o;
        o.x = *(uint32_t*)&lo; o.y = *(uint32_t*)&hi;
        *(uint2*)(g_wqk + j) = o;
        if (j < QK_N) *(float4*)(g_biasqk + j) = *(const float4*)(ipb + j);
    }
}

// merged: cvt x -> fp16 (blocks 0..12499), zero deg (blocks 12500..)
__global__ void k_init(const float* __restrict__ x) {
    int b = blockIdx.x, tid = threadIdx.x;
    if (b < 12500) {
        int idx = b * 256 + tid;
        float2 v = ((const float2*)x)[idx];
        ((__half2*)g_x16)[idx] = __floats2half2_rn(v.x, v.y);
    } else {
        int i = (b - 12500) * 256 + tid;
        if (i < N_NODES) g_deg[i] = 0;
    }
}

// ------------------------- degree / CSR build -------------------------
__global__ void k_count(const int* __restrict__ ei, int E1) {
    int e = blockIdx.x * blockDim.x + threadIdx.x;
    if (e >= E1) return;
    atomicAdd(&g_deg[ei[E1 + e]], 1);
}
__global__ void k_scanA() {
    int b = blockIdx.x, t = threadIdx.x;
    int i = b * 1024 + t;
    int v = (i < N_NODES) ? g_deg[i] : 0;
    int lane = t & 31, w = t >> 5;
    int x = v;
    #pragma unroll
    for (int o = 1; o < 32; o <<= 1) {
        int y = __shfl_up_sync(0xffffffffu, x, o);
        if (lane >= o) x += y;
    }
    __shared__ int ws[32];
    if (lane == 31) ws[w] = x;
    __syncthreads();
    if (w == 0) {
        int s = ws[lane];
        #pragma unroll
        for (int o = 1; o < 32; o <<= 1) {
            int y = __shfl_up_sync(0xffffffffu, s, o);
            if (lane >= o) s += y;
        }
        ws[lane] = s;
    }
    __syncthreads();
    int incl = x + (w > 0 ? ws[w - 1] : 0);
    if (i < N_NODES) g_cursor[i] = incl;
    if (t == 1023) g_bsums[b] = incl;
}
__global__ void k_scanB(int nblk) {
    __shared__ int sh[64];
    int t = threadIdx.x;
    int v = (t < nblk) ? g_bsums[t] : 0;
    sh[t] = v;
    __syncthreads();
    for (int o = 1; o < 64; o <<= 1) {
        int y = (t >= o) ? sh[t - o] : 0;
        __syncthreads();
        sh[t] += y;
        __syncthreads();
    }
    g_boff[t] = sh[t] - v;
}
__global__ void k_scanC() {   // + dinv fused
    int b = blockIdx.x, t = threadIdx.x;
    int i = b * 1024 + t;
    if (i < N_NODES) {
        int dg = g_deg[i];
        int inc = g_cursor[i] + g_boff[b];
        g_rowptr[i + 1] = inc;
        g_cursor[i] = inc - dg;
        g_dinv[i] = rsqrtf((float)(dg + 1));
    }
    if (i == 0) g_rowptr[0] = 0;
}
__global__ void k_scatter(const int* __restrict__ ei, int E1) {
    int e = blockIdx.x * blockDim.x + threadIdx.x;
    if (e >= E1) return;
    int pos = atomicAdd(&g_cursor[ei[E1 + e]], 1);
    g_colsrc[pos] = ei[e];
}

// ------------------------- fp16 GEMM via mma.sync, cp.async double-buffered --------
// C[M,N] = A[M,K] @ Bt[N,K]^T + cscale*bias (fp32), optional relu, output fp16.
#define STR 40
#define TILE_B (128 * STR * 2)
#define BUF_B  (2 * TILE_B)
#define GSM    (2 * BUF_B)
__global__ __launch_bounds__(256) void k_gemm(
    const __half* __restrict__ A, const __half* __restrict__ B,
    const float* __restrict__ bias, const float* __restrict__ cvec, int relu,
    __half* __restrict__ Ch, int M, int N, int K, int ldc)
{
    extern __shared__ char smdyn[];
    uint32_t sb = smem_u32(smdyn);

    int tid = threadIdx.x;
    int lane = tid & 31, w = tid >> 5;
    int wm0 = (w >> 2) * 64, wn0 = (w & 3) * 32;
    int m0 = blockIdx.y * 128, n0 = blockIdx.x * 128;

    float acc[4][4][4];
    #pragma unroll
    for (int mt = 0; mt < 4; mt++)
        #pragma unroll
        for (int nt = 0; nt < 4; nt++)
            #pragma unroll
            for (int q = 0; q < 4; q++) acc[mt][nt][q] = 0.f;

    int r8 = lane & 7, sel = lane >> 3;
    uint32_t aoff[4], boff[4];
    #pragma unroll
    for (int mt = 0; mt < 4; mt++)
        aoff[mt] = ((wm0 + mt * 16 + (sel & 1) * 8 + r8) * STR + (sel >> 1) * 8) * 2;
    int selb = sel & 1;
    #pragma unroll
    for (int nt = 0; nt < 4; nt++)
        boff[nt] = ((wn0 + nt * 8 + r8) * STR + selb * 8) * 2;

    int nch = K >> 5;

    auto stage = [&](int ch, int buf) {
        int k0 = ch << 5;
        #pragma unroll
        for (int i = 0; i < 2; i++) {
            int lin = tid + i * 256;
            int row = lin >> 2, seg = lin & 3;
            uint32_t dst = sb + buf * BUF_B + row * (STR * 2) + seg * 16;
            int gr = m0 + row;
            bool ok = gr < M;
            int grc = ok ? gr : 0;
            int gn = n0 + row;
            cp16p(dst, A + (size_t)grc * K + k0 + seg * 8, ok);
            cp16(dst + TILE_B, B + (size_t)gn * K + k0 + seg * 8);
        }
        asm volatile("cp.async.commit_group;" ::: "memory");
    };

    stage(0, 0);
    for (int ch = 0; ch < nch; ch++) {
        int buf = ch & 1;
        if (ch + 1 < nch) {
            stage(ch + 1, buf ^ 1);
            asm volatile("cp.async.wait_group 1;" ::: "memory");
        } else {
            asm volatile("cp.async.wait_group 0;" ::: "memory");
        }
        __syncthreads();
        uint32_t base = sb + buf * BUF_B;
        #pragma unroll
        for (int ks = 0; ks < 2; ks++) {
            uint32_t a[4][4], b[4][2];
            #pragma unroll
            for (int mt = 0; mt < 4; mt++)
                ldsm_x4(a[mt], base + aoff[mt] + ks * 32);
            #pragma unroll
            for (int nt = 0; nt < 4; nt++)
                ldsm_x2(b[nt], base + TILE_B + boff[nt] + ks * 32);
            #pragma unroll
            for (int mt = 0; mt < 4; mt++)
                #pragma unroll
                for (int nt = 0; nt < 4; nt++)
                    mma_f16(acc[mt][nt], a[mt], b[nt]);
        }
        __syncthreads();
    }

    int g = lane >> 2, tg = lane & 3;
    #pragma unroll
    for (int mt = 0; mt < 4; mt++) {
        int row = m0 + wm0 + mt * 16 + g;
        float c0 = 1.f, c1 = 1.f;
        if (cvec) {
            c0 = (row < M) ? cvec[row] : 0.f;
            c1 = (row + 8 < M) ? cvec[row + 8] : 0.f;
        }
        #pragma unroll
        for (int nt = 0; nt < 4; nt++) {
            int col = n0 + wn0 + nt * 8 + tg * 2;
            float2 bv = *(const float2*)(bias + col);
            float v00 = acc[mt][nt][0] + c0 * bv.x, v01 = acc[mt][nt][1] + c0 * bv.y;
            float v10 = acc[mt][nt][2] + c1 * bv.x, v11 = acc[mt][nt][3] + c1 * bv.y;
            if (relu) {
                v00 = fmaxf(v00, 0.f); v01 = fmaxf(v01, 0.f);
                v10 = fmaxf(v10, 0.f); v11 = fmaxf(v11, 0.f);
            }
            if (row < M)
                *(__half2*)(Ch + (size_t)row * ldc + col) = __floats2half2_rn(v00, v01);
            if (row + 8 < M)
                *(__half2*)(Ch + (size_t)(row + 8) * ldc + col) = __floats2half2_rn(v10, v11);
        }
    }
}

// ------------------------- aggregations -------------------------
// agg_x: xa = P.x (128 ch), also c[n] = dinv[n]*sum(dinv[src]) + dinv[n]^2
__global__ void k_aggx(const __half* __restrict__ xin) {
    int n = blockIdx.x * 8 + (threadIdx.x >> 5);
    int lane = threadIdx.x & 31;
    if (n >= N_NODES) return;
    int beg = g_rowptr[n], end = g_rowptr[n + 1];
    const uint2* tv = (const uint2*)xin;   // row = 32 uint2 (256B)
    float a0 = 0.f, a1 = 0.f, a2 = 0.f, a3 = 0.f, sw = 0.f;
    #pragma unroll 4
    for (int j = beg; j < end; j++) {
        int s = g_colsrc[j];
        float w = g_dinv[s];
        sw += w;
        uint2 v = tv[(size_t)s * 32 + lane];
        float2 f01 = __half22float2(*(const __half2*)&v.x);
        float2 f23 = __half22float2(*(const __half2*)&v.y);
        a0 += w * f01.x; a1 += w * f01.y; a2 += w * f23.x; a3 += w * f23.y;
    }
    float d = g_dinv[n], d2 = d * d;
    uint2 sv = tv[(size_t)n * 32 + lane];
    float2 s01 = __half22float2(*(const __half2*)&sv.x);
    float2 s23 = __half22float2(*(const __half2*)&sv.y);
    uint2 o;
    *(__half2*)&o.x = __floats2half2_rn(d * a0 + d2 * s01.x, d * a1 + d2 * s01.y);
    *(__half2*)&o.y = __floats2half2_rn(d * a2 + d2 * s23.x, d * a3 + d2 * s23.y);
    ((uint2*)g_xa)[(size_t)n * 32 + lane] = o;
    if (lane == 0) g_c[n] = d * sw + d2;
}

// agg_h: ha = P.h (256 ch); 4 nodes per 256-thread block
__global__ void k_aggh(const __half* __restrict__ tin) {
    int n = blockIdx.x * 4 + (threadIdx.x >> 6);
    int t = threadIdx.x & 63;
    if (n >= N_NODES) return;
    int beg = g_rowptr[n], end = g_rowptr[n + 1];
    const uint2* tv = (const uint2*)tin;   // row = 64 uint2 (512B)
    float a0 = 0.f, a1 = 0.f, a2 = 0.f, a3 = 0.f;
    #pragma unroll 4
    for (int j = beg; j < end; j++) {
        int s = g_colsrc[j];
        float w = g_dinv[s];
        uint2 v = tv[(size_t)s * 64 + t];
        float2 f01 = __half22float2(*(const __half2*)&v.x);
        float2 f23 = __half22float2(*(const __half2*)&v.y);
        a0 += w * f01.x; a1 += w * f01.y; a2 += w * f23.x; a3 += w * f23.y;
    }
    float d = g_dinv[n], d2 = d * d;
    uint2 sv = tv[(size_t)n * 64 + t];
    float2 s01 = __half22float2(*(const __half2*)&sv.x);
    float2 s23 = __half22float2(*(const __half2*)&sv.y);
    uint2 o;
    *(__half2*)&o.x = __floats2half2_rn(d * a0 + d2 * s01.x, d * a1 + d2 * s01.y);
    *(__half2*)&o.y = __floats2half2_rn(d * a2 + d2 * s23.x, d * a3 + d2 * s23.y);
    ((uint2*)g_ha)[(size_t)n * 64 + t] = o;
}

// ------------------------- per-node self scores + folded V -------------------------
__global__ void k_qkself() {
    int n = (blockIdx.x * blockDim.x + threadIdx.x) >> 5;
    int lane = threadIdx.x & 31;
    if (n >= N_NODES) return;
    const uint4* qk = (const uint4*)(g_qkvh + (size_t)n * QK_N);
    uint4 qv = qk[lane];
    uint4 kv = qk[32 + lane];
    const __half2* qh = (const __half2*)&qv;
    const __half2* kh = (const __half2*)&kv;
    float d = 0.f;
    #pragma unroll
    for (int j = 0; j < 4; j++) {
        float2 a = __half22float2(qh[j]);
        float2 b = __half22float2(kh[j]);
        d += a.x * b.x + a.y * b.y;
    }
    #pragma unroll
    for (int m = 1; m <= 4; m <<= 1) d += __shfl_xor_sync(0xffffffffu, d, m);
    if ((lane & 7) == 0) g_qkself[n * 4 + (lane >> 3)] = d;

    // folded V: vw = z . wv + bvw  (lane owns channels lane*8..+7)
    const uint4* zr = (const uint4*)(g_z16 + (size_t)n * HID);
    uint4 zv = zr[lane];
    const __half2* zh = (const __half2*)&zv;
    float zc[8];
    #pragma unroll
    for (int j = 0; j < 4; j++) {
        float2 f = __half22float2(zh[j]);
        zc[2 * j] = f.x; zc[2 * j + 1] = f.y;
    }
    const float4* wv4 = (const float4*)g_wv;
    float p0 = 0.f, p1 = 0.f, p2 = 0.f, p3 = 0.f;
    #pragma unroll
    for (int i = 0; i < 8; i++) {
        float4 wv = wv4[lane * 8 + i];
        p0 += zc[i] * wv.x; p1 += zc[i] * wv.y;
        p2 += zc[i] * wv.z; p3 += zc[i] * wv.w;
    }
    #pragma unroll
    for (int m = 16; m > 0; m >>= 1) {
        p0 += __shfl_xor_sync(0xffffffffu, p0, m);
        p1 += __shfl_xor_sync(0xffffffffu, p1, m);
        p2 += __shfl_xor_sync(0xffffffffu, p2, m);
        p3 += __shfl_xor_sync(0xffffffffu, p3, m);
    }
    if (lane == 0) {
        g_vw[n * 4 + 0] = p0 + g_bvw[0];
        g_vw[n * 4 + 1] = p1 + g_bvw[1];
        g_vw[n * 4 + 2] = p2 + g_bvw[2];
        g_vw[n * 4 + 3] = p3 + g_bvw[3];
    }
}

// ------------------------- per-prediction-edge attention -------------------------
__global__ void k_edge(const int* __restrict__ eip, float* __restrict__ out, int E2) {
    int w = (blockIdx.x * blockDim.x + threadIdx.x) >> 5;
    int lane = threadIdx.x & 31;
    if (w >= E2) return;
    int sp = eip[w];
    int dp = eip[E2 + w];
    const uint4* Qr = (const uint4*)(g_qkvh + (size_t)sp * QK_N);
    const uint4* Kr = (const uint4*)(g_qkvh + (size_t)dp * QK_N);
    uint4 qv = Qr[lane];
    uint4 kv = Kr[32 + lane];
    const __half2* qh = (const __half2*)&qv;
    const __half2* kh = (const __half2*)&kv;
    float d = 0.f;
    #pragma unroll
    for (int j = 0; j < 4; j++) {
        float2 a = __half22float2(qh[j]);
        float2 b = __half22float2(kh[j]);
        d += a.x * b.x + a.y * b.y;
    }
    #pragma unroll
    for (int m = 1; m <= 4; m <<= 1) d += __shfl_xor_sync(0xffffffffu, d, m);
    float s0 = __shfl_sync(0xffffffffu, d, 0);
    float s1 = __shfl_sync(0xffffffffu, d, 8);
    float s2 = __shfl_sync(0xffffffffu, d, 16);
    float s3 = __shfl_sync(0xffffffffu, d, 24);
    if (lane == 0) {
        float sc[4] = { s0, s1, s2, s3 };
        const float* vws = g_vw + (size_t)sp * 4;
        const float* vwd = g_vw + (size_t)dp * 4;
        const float* qks = g_qkself + (size_t)sp * 4;
        float acc = g_bsum;
        #pragma unroll
        for (int h = 0; h < 4; h++) {
            float a = 1.f / (1.f + expf((sc[h] - qks[h]) * 0.125f));
            acc += a * vws[h] + (1.f - a) * vwd[h];
        }
        out[w] = 1.f / (1.f + expf(-acc));
    }
}

// ------------------------- launch -------------------------
extern "C" void kernel_launch(void* const* d_in, const int* in_sizes, int n_in,
                              void* d_out, int out_size) {
    const float* x   = (const float*)d_in[0];
    const int* ei    = (const int*)d_in[1];
    const int* eip   = (const int*)d_in[2];
    const float* W1  = (const float*)d_in[3];
    const float* b1  = (const float*)d_in[4];
    const float* W2  = (const float*)d_in[5];
    const float* b2  = (const float*)d_in[6];
    const float* ipw = (const float*)d_in[7];
    const float* ipb = (const float*)d_in[8];
    const float* opw = (const float*)d_in[9];
    const float* opb = (const float*)d_in[10];
    float* out       = (float*)d_out;

    int E1 = in_sizes[1] / 2;
    int E2 = in_sizes[2] / 2;

    static bool attr_set = false;
    if (!attr_set) {
        cudaFuncSetAttribute(k_gemm, cudaFuncAttributeMaxDynamicSharedMemorySize, GSM);
        attr_set = true;
    }

    float *pBqk, *pC;
    __half *pXa, *pH, *pHa, *pZ, *pQKV, *pW1, *pW2, *pWqk, *pX;
    cudaGetSymbolAddress((void**)&pX,   g_x16);
    cudaGetSymbolAddress((void**)&pXa,  g_xa);
    cudaGetSymbolAddress((void**)&pH,   g_h16);
    cudaGetSymbolAddress((void**)&pHa,  g_ha);
    cudaGetSymbolAddress((void**)&pZ,   g_z16);
    cudaGetSymbolAddress((void**)&pQKV, g_qkvh);
    cudaGetSymbolAddress((void**)&pW1,  g_w1);
    cudaGetSymbolAddress((void**)&pW2,  g_w2);
    cudaGetSymbolAddress((void**)&pWqk, g_wqk);
    cudaGetSymbolAddress((void**)&pBqk, g_biasqk);
    cudaGetSymbolAddress((void**)&pC,   g_c);

    // prep
    k_wsum_vw<<<1, 256>>>(opw, opb, ipw, ipb);
    k_prep_w<<<224, 256>>>(W1, W2, ipw, ipb);
    k_init<<<12500 + 196, 256>>>(x);

    // CSR
    k_count<<<(E1 + 255) / 256, 256>>>(ei, E1);
    int nblk = (N_NODES + 1023) / 1024;
    k_scanA<<<nblk, 1024>>>();
    k_scanB<<<1, 64>>>(nblk);
    k_scanC<<<nblk, 1024>>>();
    k_scatter<<<(E1 + 255) / 256, 256>>>(ei, E1);

    dim3 g1(HID / 128, (N_NODES + 127) / 128);
    dim3 g3(QK_N / 128, (N_NODES + 127) / 128);

    // layer 1: xa = P.x ; h = relu(xa@W1 + c*b1)
    k_aggx<<<(N_NODES + 7) / 8, 256>>>(pX);
    k_gemm<<<g1, 256, GSM>>>(pXa, pW1, b1, pC, 1, pH, N_NODES, HID, IN_CH, HID);

    // layer 2: ha = P.h ; z = ha@W2 + c*b2
    k_aggh<<<(N_NODES + 3) / 4, 256>>>(pH);
    k_gemm<<<g1, 256, GSM>>>(pHa, pW2, b2, pC, 0, pZ, N_NODES, HID, HID, HID);

    // QK projection
    k_gemm<<<g3, 256, GSM>>>(pZ, pWqk, pBqk, nullptr, 0, pQKV, N_NODES, QK_N, HID, QK_N);

    // self scores + folded V, then per-edge attention
    k_qkself<<<(N_NODES * 32 + 255) / 256, 256>>>();
    k_edge<<<((size_t)E2 * 32 + 255) / 256, 256>>>(eip, out, E2);
}